// round 15
// baseline (speedup 1.0000x reference)
#include <cuda_runtime.h>
#include <cuda_bf16.h>
#include <cstdint>

#define BATCH 4
#define SLEN  2048
#define DM    1024
#define M_ALL (BATCH * SLEN)   // 8192

// ---------------------------------------------------------------------------
// Scratch (device globals — no runtime allocation allowed)
// ---------------------------------------------------------------------------
__device__ __nv_bfloat16 g_Xhi[M_ALL * DM];
__device__ __nv_bfloat16 g_Xlo[M_ALL * DM];
__device__ __nv_bfloat16 g_Wthi[3][DM * DM];
__device__ __nv_bfloat16 g_Wtlo[3][DM * DM];
__device__ __nv_bfloat16 g_Qhi[M_ALL * DM];
__device__ __nv_bfloat16 g_Qlo[M_ALL * DM];
__device__ __nv_bfloat16 g_Khi[M_ALL * DM];
__device__ __nv_bfloat16 g_Klo[M_ALL * DM];
__device__ float         g_Vf [M_ALL * DM];
__device__ __nv_bfloat16 g_Vthi[(size_t)BATCH * DM * SLEN];
__device__ __nv_bfloat16 g_Vtlo[(size_t)BATCH * DM * SLEN];
__device__ float         g_S  [(size_t)BATCH * SLEN * SLEN];
__device__ __nv_bfloat16 g_Phi[(size_t)BATCH * SLEN * SLEN];
__device__ __nv_bfloat16 g_Plo[(size_t)BATCH * SLEN * SLEN];

// ---------------------------------------------------------------------------
// Helpers (base-PTX only: mma.sync + cp.async)
// ---------------------------------------------------------------------------
__device__ __forceinline__ uint32_t smem_u32(const void* p) {
    uint32_t a;
    asm("{ .reg .u64 t; cvta.to.shared.u64 t, %1; cvt.u32.u64 %0, t; }"
        : "=r"(a) : "l"(p));
    return a;
}

__device__ __forceinline__ uint32_t lds32(uint32_t addr) {
    uint32_t v;
    asm volatile("ld.shared.b32 %0, [%1];" : "=r"(v) : "r"(addr));
    return v;
}

__device__ __forceinline__ void cp16(uint32_t dst, const void* src) {
    asm volatile("cp.async.cg.shared.global [%0], [%1], 16;"
                 :: "r"(dst), "l"(src) : "memory");
}

__device__ __forceinline__ void mma_bf16(float* c, const uint32_t* a, const uint32_t* b) {
    asm volatile(
        "mma.sync.aligned.m16n8k16.row.col.f32.bf16.bf16.f32 "
        "{%0,%1,%2,%3}, {%4,%5,%6,%7}, {%8,%9}, {%0,%1,%2,%3};"
        : "+f"(c[0]), "+f"(c[1]), "+f"(c[2]), "+f"(c[3])
        : "r"(a[0]), "r"(a[1]), "r"(a[2]), "r"(a[3]), "r"(b[0]), "r"(b[1]));
}

// ---------------------------------------------------------------------------
// HMMA bf16x3 GEMM:  C[M,N] = alpha * (A_hi+A_lo)[M,K] @ (B_hi+B_lo)[N,K]^T
// Both operands K-major. CTA tile 128x128, K-chunk 32, 8 warps (warp tile
// 32x64), 2-stage cp.async pipeline, 2 CTAs/SM for latency hiding.
// 80B-padded SMEM rows. 3 MMA terms: hi*hi + hi*lo + lo*hi.
//   OUT_SPLIT=1 : epilogue emits bf16 hi/lo pair instead of fp32
//   TRI=1       : skip CTAs above the diagonal (scores QK^T, masked anyway)
//   KCAP=1      : causal K-range cap, nchunk = (row0+128)/32
// All call sites guarantee nchunk >= 4.
// ---------------------------------------------------------------------------
#define TILE_B    10240           // 128 rows x 80 B
#define STAGE_B   (4 * TILE_B)    // Ahi, Alo, Bhi, Blo
#define NSTAGE    2
#define GEMM_SMEM (NSTAGE * STAGE_B)   // 81920 B -> 2 CTAs/SM

template <int OUT_SPLIT, int TRI, int KCAP>
__global__ void __launch_bounds__(256, 2) gemm_mma_bf16x3(
    const __nv_bfloat16* __restrict__ Ahi, const __nv_bfloat16* __restrict__ Alo,
    const __nv_bfloat16* __restrict__ Bhi, const __nv_bfloat16* __restrict__ Blo,
    float* __restrict__ C, __nv_bfloat16* __restrict__ Chi, __nv_bfloat16* __restrict__ Clo,
    int M, int N, int K, size_t sAz, size_t sBz, size_t sCz, float alpha)
{
    if (TRI && (int)blockIdx.x > (int)blockIdx.y) return;  // fully-masked tile

    extern __shared__ __align__(16) char smem[];
    const uint32_t sb = smem_u32(smem);
    const int tid  = threadIdx.x;
    const int lane = tid & 31;
    const int wid  = tid >> 5;
    const int wm   = wid & 3;    // 4 warps along M
    const int wn   = wid >> 2;   // 2 warps along N

    Ahi += (size_t)blockIdx.z * sAz;  Alo += (size_t)blockIdx.z * sAz;
    Bhi += (size_t)blockIdx.z * sBz;  Blo += (size_t)blockIdx.z * sBz;

    const int row0 = blockIdx.y * 128;
    const int col0 = blockIdx.x * 128;
    const int kEff = KCAP ? (row0 + 128 < K ? row0 + 128 : K) : K;
    const int nchunk = kEff >> 5;

    // per-chunk loader: 4 tiles of 128 rows x 32 bf16 (64 B), padded to 80 B
    auto load_chunk = [&](int c, int s) {
        const int k0 = c << 5;
        const __nv_bfloat16* srcs[4] = {
            Ahi + (size_t)row0 * K + k0, Alo + (size_t)row0 * K + k0,
            Bhi + (size_t)col0 * K + k0, Blo + (size_t)col0 * K + k0 };
        const uint32_t dbase = sb + s * STAGE_B;
        #pragma unroll
        for (int t = 0; t < 4; ++t) {
            #pragma unroll
            for (int rep = 0; rep < 2; ++rep) {
                int idx = tid + rep * 256;      // 0..511
                int r = idx >> 2;               // row 0..127
                int q = idx & 3;                // 16B quarter of the 64B row
                cp16(dbase + t * TILE_B + r * 80 + q * 16,
                     srcs[t] + (size_t)r * K + q * 8);
            }
        }
    };

    float acc[2][8][4];
    #pragma unroll
    for (int mi = 0; mi < 2; ++mi)
        #pragma unroll
        for (int ni = 0; ni < 8; ++ni)
            #pragma unroll
            for (int j = 0; j < 4; ++j) acc[mi][ni][j] = 0.f;

    // prologue: prefetch 1 chunk
    load_chunk(0, 0);
    asm volatile("cp.async.commit_group;" ::: "memory");

    const int r   = lane >> 2;          // fragment row
    const int kq2 = (lane & 3) * 2;     // fragment k pair

    for (int c = 0; c < nchunk; ++c) {
        if (c + 1 < nchunk) load_chunk(c + 1, (c + 1) & 1);
        asm volatile("cp.async.commit_group;" ::: "memory");
        asm volatile("cp.async.wait_group 1;" ::: "memory");
        __syncthreads();

        const uint32_t s0 = sb + (c & 1) * STAGE_B;

        #pragma unroll
        for (int ks = 0; ks < 2; ++ks) {
            const uint32_t kb = (uint32_t)(ks * 16 + kq2) * 2;   // byte offset in k
            uint32_t ah[2][4], al[2][4], bh[8][2], bl[8][2];

            #pragma unroll
            for (int mi = 0; mi < 2; ++mi) {
                uint32_t base = s0 + (uint32_t)(wm * 32 + mi * 16 + r) * 80 + kb;
                ah[mi][0] = lds32(base);        ah[mi][1] = lds32(base + 640);
                ah[mi][2] = lds32(base + 16);   ah[mi][3] = lds32(base + 656);
                base += TILE_B;
                al[mi][0] = lds32(base);        al[mi][1] = lds32(base + 640);
                al[mi][2] = lds32(base + 16);   al[mi][3] = lds32(base + 656);
            }
            #pragma unroll
            for (int ni = 0; ni < 8; ++ni) {
                uint32_t base = s0 + 2 * TILE_B + (uint32_t)(wn * 64 + ni * 8 + r) * 80 + kb;
                bh[ni][0] = lds32(base);        bh[ni][1] = lds32(base + 16);
                base += TILE_B;
                bl[ni][0] = lds32(base);        bl[ni][1] = lds32(base + 16);
            }

            // 3 precision terms across 16 independent accumulators
            #pragma unroll
            for (int mi = 0; mi < 2; ++mi)
                #pragma unroll
                for (int ni = 0; ni < 8; ++ni)
                    mma_bf16(acc[mi][ni], ah[mi], bh[ni]);
            #pragma unroll
            for (int mi = 0; mi < 2; ++mi)
                #pragma unroll
                for (int ni = 0; ni < 8; ++ni)
                    mma_bf16(acc[mi][ni], ah[mi], bl[ni]);
            #pragma unroll
            for (int mi = 0; mi < 2; ++mi)
                #pragma unroll
                for (int ni = 0; ni < 8; ++ni)
                    mma_bf16(acc[mi][ni], al[mi], bh[ni]);
        }
        __syncthreads();
    }

    // Epilogue
    #pragma unroll
    for (int mi = 0; mi < 2; ++mi) {
        const int rowA = row0 + wm * 32 + mi * 16 + r;
        #pragma unroll
        for (int ni = 0; ni < 8; ++ni) {
            const int col = col0 + wn * 64 + ni * 8 + kq2;
            float v0 = acc[mi][ni][0] * alpha;
            float v1 = acc[mi][ni][1] * alpha;
            float v2 = acc[mi][ni][2] * alpha;
            float v3 = acc[mi][ni][3] * alpha;
            if (OUT_SPLIT) {
                __nv_bfloat16* ph = Chi + (size_t)blockIdx.z * sCz;
                __nv_bfloat16* pl = Clo + (size_t)blockIdx.z * sCz;
                __nv_bfloat16 h0 = __float2bfloat16(v0), h1 = __float2bfloat16(v1);
                __nv_bfloat16 h2 = __float2bfloat16(v2), h3 = __float2bfloat16(v3);
                __nv_bfloat162 hp0; hp0.x = h0; hp0.y = h1;
                __nv_bfloat162 hp1; hp1.x = h2; hp1.y = h3;
                __nv_bfloat162 lp0, lp1;
                lp0.x = __float2bfloat16(v0 - __bfloat162float(h0));
                lp0.y = __float2bfloat16(v1 - __bfloat162float(h1));
                lp1.x = __float2bfloat16(v2 - __bfloat162float(h2));
                lp1.y = __float2bfloat16(v3 - __bfloat162float(h3));
                *(__nv_bfloat162*)(ph + (size_t)rowA * N + col)       = hp0;
                *(__nv_bfloat162*)(pl + (size_t)rowA * N + col)       = lp0;
                *(__nv_bfloat162*)(ph + (size_t)(rowA + 8) * N + col) = hp1;
                *(__nv_bfloat162*)(pl + (size_t)(rowA + 8) * N + col) = lp1;
            } else {
                float* pc = C + (size_t)blockIdx.z * sCz;
                float2 f0 = {v0, v1}, f1 = {v2, v3};
                *(float2*)(pc + (size_t)rowA * N + col)       = f0;
                *(float2*)(pc + (size_t)(rowA + 8) * N + col) = f1;
            }
        }
    }
}

// ---------------------------------------------------------------------------
// fp32 -> bf16 hi/lo split (elementwise, vectorized)
// ---------------------------------------------------------------------------
__global__ void split_f32(const float* __restrict__ src,
                          __nv_bfloat16* __restrict__ hi,
                          __nv_bfloat16* __restrict__ lo, int n4)
{
    int i = blockIdx.x * blockDim.x + threadIdx.x;
    if (i >= n4) return;
    float4 v = ((const float4*)src)[i];
    __nv_bfloat16 h0 = __float2bfloat16(v.x), h1 = __float2bfloat16(v.y);
    __nv_bfloat16 h2 = __float2bfloat16(v.z), h3 = __float2bfloat16(v.w);
    __nv_bfloat162 hp0; hp0.x = h0; hp0.y = h1;
    __nv_bfloat162 hp1; hp1.x = h2; hp1.y = h3;
    __nv_bfloat162 lp0, lp1;
    lp0.x = __float2bfloat16(v.x - __bfloat162float(h0));
    lp0.y = __float2bfloat16(v.y - __bfloat162float(h1));
    lp1.x = __float2bfloat16(v.z - __bfloat162float(h2));
    lp1.y = __float2bfloat16(v.w - __bfloat162float(h3));
    ((__nv_bfloat162*)hi)[2 * i]     = hp0;
    ((__nv_bfloat162*)hi)[2 * i + 1] = hp1;
    ((__nv_bfloat162*)lo)[2 * i]     = lp0;
    ((__nv_bfloat162*)lo)[2 * i + 1] = lp1;
}

// ---------------------------------------------------------------------------
// fp32 [R,C] -> transposed bf16 hi/lo [C,R] (32x32 smem tile)
// ---------------------------------------------------------------------------
__global__ void transpose_split(const float* __restrict__ src,
                                __nv_bfloat16* __restrict__ hi,
                                __nv_bfloat16* __restrict__ lo,
                                int R, int C, size_t sSrc, size_t sDst)
{
    __shared__ float t[32][33];
    src += (size_t)blockIdx.z * sSrc;
    const int tx = threadIdx.x, ty = threadIdx.y;
    const int x  = blockIdx.x * 32 + tx;
    const int y0 = blockIdx.y * 32 + ty;
    #pragma unroll
    for (int i = 0; i < 32; i += 8)
        t[ty + i][tx] = src[(size_t)(y0 + i) * C + x];
    __syncthreads();
    const int ox  = blockIdx.y * 32 + tx;
    const int oy0 = blockIdx.x * 32 + ty;
    #pragma unroll
    for (int i = 0; i < 32; i += 8) {
        float v = t[tx][ty + i];
        __nv_bfloat16 h = __float2bfloat16(v);
        size_t idx = (size_t)blockIdx.z * sDst + (size_t)(oy0 + i) * R + ox;
        hi[idx] = h;
        lo[idx] = __float2bfloat16(v - __bfloat162float(h));
    }
}

// ---------------------------------------------------------------------------
// Causal softmax: reads fp32 scores (j<=i only), writes bf16 hi/lo P.
// Only writes j < blockend(i) — PV's causal K-cap never reads beyond the
// diagonal 128-block, so the rest of the row can stay garbage.
// ---------------------------------------------------------------------------
__global__ __launch_bounds__(256) void softmax_causal_split(
    const float* __restrict__ S,
    __nv_bfloat16* __restrict__ Phi, __nv_bfloat16* __restrict__ Plo)
{
    const int i = blockIdx.x;
    const int b = blockIdx.y;
    const size_t base = ((size_t)b * SLEN + i) * SLEN;
    const float* row = S + base;
    const int limit = ((i >> 7) + 1) << 7;   // end of diagonal 128-block

    __shared__ float sh[SLEN];
    __shared__ float red[256];
    const int tid = threadIdx.x;

    float mx = -1e30f;
    for (int j = tid; j < limit; j += 256) {
        float v = (j <= i) ? row[j] : -1e30f;
        sh[j] = v;
        mx = fmaxf(mx, v);
    }
    red[tid] = mx;
    __syncthreads();
    for (int s = 128; s > 0; s >>= 1) {
        if (tid < s) red[tid] = fmaxf(red[tid], red[tid + s]);
        __syncthreads();
    }
    mx = red[0];
    __syncthreads();

    float sum = 0.f;
    for (int j = tid; j < limit; j += 256) {
        float e = (j <= i) ? expf(sh[j] - mx) : 0.f;
        sh[j] = e;
        sum += e;
    }
    red[tid] = sum;
    __syncthreads();
    for (int s = 128; s > 0; s >>= 1) {
        if (tid < s) red[tid] += red[tid + s];
        __syncthreads();
    }
    const float inv = 1.f / red[0];
    __syncthreads();

    for (int j = tid; j < limit; j += 256) {
        float p = sh[j] * inv;
        __nv_bfloat16 h = __float2bfloat16(p);
        Phi[base + j] = h;
        Plo[base + j] = __float2bfloat16(p - __bfloat162float(h));
    }
}

// ---------------------------------------------------------------------------
extern "C" void kernel_launch(void* const* d_in, const int* in_sizes, int n_in,
                              void* d_out, int out_size)
{
    const float* X  = (const float*)d_in[0];
    const float* Wq = (const float*)d_in[1];
    const float* Wk = (const float*)d_in[2];
    const float* Wv = (const float*)d_in[3];
    float* out = (float*)d_out;

    __nv_bfloat16 *Xhi, *Xlo, *Wthi, *Wtlo, *Qhi, *Qlo, *Khi, *Klo;
    __nv_bfloat16 *Vthi, *Vtlo, *Phi, *Plo;
    float *Vf, *Sc;
    cudaGetSymbolAddress((void**)&Xhi, g_Xhi);
    cudaGetSymbolAddress((void**)&Xlo, g_Xlo);
    cudaGetSymbolAddress((void**)&Wthi, g_Wthi);
    cudaGetSymbolAddress((void**)&Wtlo, g_Wtlo);
    cudaGetSymbolAddress((void**)&Qhi, g_Qhi);
    cudaGetSymbolAddress((void**)&Qlo, g_Qlo);
    cudaGetSymbolAddress((void**)&Khi, g_Khi);
    cudaGetSymbolAddress((void**)&Klo, g_Klo);
    cudaGetSymbolAddress((void**)&Vf,  g_Vf);
    cudaGetSymbolAddress((void**)&Vthi, g_Vthi);
    cudaGetSymbolAddress((void**)&Vtlo, g_Vtlo);
    cudaGetSymbolAddress((void**)&Sc,  g_S);
    cudaGetSymbolAddress((void**)&Phi, g_Phi);
    cudaGetSymbolAddress((void**)&Plo, g_Plo);

    cudaFuncSetAttribute(gemm_mma_bf16x3<0,0,0>, cudaFuncAttributeMaxDynamicSharedMemorySize, GEMM_SMEM);
    cudaFuncSetAttribute(gemm_mma_bf16x3<1,0,0>, cudaFuncAttributeMaxDynamicSharedMemorySize, GEMM_SMEM);
    cudaFuncSetAttribute(gemm_mma_bf16x3<0,1,0>, cudaFuncAttributeMaxDynamicSharedMemorySize, GEMM_SMEM);
    cudaFuncSetAttribute(gemm_mma_bf16x3<0,0,1>, cudaFuncAttributeMaxDynamicSharedMemorySize, GEMM_SMEM);

    const size_t WSZ = (size_t)DM * DM;

    // 1. X -> bf16 split
    split_f32<<<(M_ALL * DM / 4 + 255) / 256, 256>>>(X, Xhi, Xlo, M_ALL * DM / 4);

    // 2. W -> transposed bf16 split ([n][k])
    dim3 tb(32, 8);
    transpose_split<<<dim3(DM / 32, DM / 32, 1), tb>>>(Wq, Wthi + 0 * WSZ, Wtlo + 0 * WSZ, DM, DM, 0, 0);
    transpose_split<<<dim3(DM / 32, DM / 32, 1), tb>>>(Wk, Wthi + 1 * WSZ, Wtlo + 1 * WSZ, DM, DM, 0, 0);
    transpose_split<<<dim3(DM / 32, DM / 32, 1), tb>>>(Wv, Wthi + 2 * WSZ, Wtlo + 2 * WSZ, DM, DM, 0, 0);

    // 3. QKV projections; Q,K epilogue emits bf16 split directly
    dim3 gq(DM / 128, M_ALL / 128, 1);
    gemm_mma_bf16x3<1,0,0><<<gq, 256, GEMM_SMEM>>>(Xhi, Xlo, Wthi + 0 * WSZ, Wtlo + 0 * WSZ,
                                                   nullptr, Qhi, Qlo, M_ALL, DM, DM, 0, 0, 0, 1.f);
    gemm_mma_bf16x3<1,0,0><<<gq, 256, GEMM_SMEM>>>(Xhi, Xlo, Wthi + 1 * WSZ, Wtlo + 1 * WSZ,
                                                   nullptr, Khi, Klo, M_ALL, DM, DM, 0, 0, 0, 1.f);
    gemm_mma_bf16x3<0,0,0><<<gq, 256, GEMM_SMEM>>>(Xhi, Xlo, Wthi + 2 * WSZ, Wtlo + 2 * WSZ,
                                                   Vf, nullptr, nullptr, M_ALL, DM, DM, 0, 0, 0, 1.f);

    // 4. V -> per-batch transposed bf16 split ([e][s])
    transpose_split<<<dim3(DM / 32, SLEN / 32, BATCH), tb>>>(
        Vf, Vthi, Vtlo, SLEN, DM, (size_t)SLEN * DM, (size_t)DM * SLEN);

    // 5. Scores: S = (Q @ K^T) / 32, lower-triangle tiles only (TRI=1)
    dim3 gs(SLEN / 128, SLEN / 128, BATCH);
    gemm_mma_bf16x3<0,1,0><<<gs, 256, GEMM_SMEM>>>(Qhi, Qlo, Khi, Klo, Sc, nullptr, nullptr,
                                                   SLEN, SLEN, DM,
                                                   (size_t)SLEN * DM, (size_t)SLEN * DM,
                                                   (size_t)SLEN * SLEN, 1.f / 32.f);

    // 6. Causal softmax -> bf16-split P (writes only up to diagonal block end)
    softmax_causal_split<<<dim3(SLEN, BATCH), 256>>>(Sc, Phi, Plo);

    // 7. Output: out = P @ V^T with causal K-cap (KCAP=1)
    dim3 go(DM / 128, SLEN / 128, BATCH);
    gemm_mma_bf16x3<0,0,1><<<go, 256, GEMM_SMEM>>>(Phi, Plo, Vthi, Vtlo, out, nullptr, nullptr,
                                                   SLEN, DM, SLEN,
                                                   (size_t)SLEN * SLEN, (size_t)DM * SLEN,
                                                   (size_t)SLEN * DM, 1.f);
}

// round 16
// speedup vs baseline: 1.0017x; 1.0017x over previous
#include <cuda_runtime.h>
#include <cuda_bf16.h>
#include <cstdint>

#define BATCH 4
#define SLEN  2048
#define DM    1024
#define M_ALL (BATCH * SLEN)   // 8192

// ---------------------------------------------------------------------------
// Scratch (device globals — no runtime allocation allowed)
// ---------------------------------------------------------------------------
__device__ __nv_bfloat16 g_Xhi[M_ALL * DM];
__device__ __nv_bfloat16 g_Xlo[M_ALL * DM];
__device__ __nv_bfloat16 g_Wthi[3][DM * DM];
__device__ __nv_bfloat16 g_Wtlo[3][DM * DM];
__device__ __nv_bfloat16 g_Qhi[M_ALL * DM];
__device__ __nv_bfloat16 g_Qlo[M_ALL * DM];
__device__ __nv_bfloat16 g_Khi[M_ALL * DM];
__device__ __nv_bfloat16 g_Klo[M_ALL * DM];
__device__ float         g_Vf [M_ALL * DM];
__device__ __nv_bfloat16 g_Vthi[(size_t)BATCH * DM * SLEN];
__device__ __nv_bfloat16 g_Vtlo[(size_t)BATCH * DM * SLEN];
__device__ float         g_S  [(size_t)BATCH * SLEN * SLEN];
__device__ __nv_bfloat16 g_Phi[(size_t)BATCH * SLEN * SLEN];
__device__ __nv_bfloat16 g_Plo[(size_t)BATCH * SLEN * SLEN];

// ---------------------------------------------------------------------------
// Helpers (base-PTX only: mma.sync + cp.async)
// ---------------------------------------------------------------------------
__device__ __forceinline__ uint32_t smem_u32(const void* p) {
    uint32_t a;
    asm("{ .reg .u64 t; cvta.to.shared.u64 t, %1; cvt.u32.u64 %0, t; }"
        : "=r"(a) : "l"(p));
    return a;
}

__device__ __forceinline__ uint32_t lds32(uint32_t addr) {
    uint32_t v;
    asm volatile("ld.shared.b32 %0, [%1];" : "=r"(v) : "r"(addr));
    return v;
}

__device__ __forceinline__ void cp16(uint32_t dst, const void* src) {
    asm volatile("cp.async.cg.shared.global [%0], [%1], 16;"
                 :: "r"(dst), "l"(src) : "memory");
}

__device__ __forceinline__ void mma_bf16(float* c, const uint32_t* a, const uint32_t* b) {
    asm volatile(
        "mma.sync.aligned.m16n8k16.row.col.f32.bf16.bf16.f32 "
        "{%0,%1,%2,%3}, {%4,%5,%6,%7}, {%8,%9}, {%0,%1,%2,%3};"
        : "+f"(c[0]), "+f"(c[1]), "+f"(c[2]), "+f"(c[3])
        : "r"(a[0]), "r"(a[1]), "r"(a[2]), "r"(a[3]), "r"(b[0]), "r"(b[1]));
}

// ---------------------------------------------------------------------------
// HMMA bf16x3 GEMM:  C[M,N] = alpha * (A_hi+A_lo)[M,K] @ (B_hi+B_lo)[N,K]^T
// Both operands K-major. CTA tile 128x128, K-chunk 32, 8 warps (warp tile
// 32x64), 2-stage cp.async pipeline, 2 CTAs/SM for latency hiding.
// 80B-padded SMEM rows. 3 MMA terms: hi*hi + hi*lo + lo*hi.
//   OUT_SPLIT=1 : epilogue emits bf16 hi/lo pair instead of fp32
//   TRI=1       : skip CTAs above the diagonal (scores QK^T, masked anyway)
//   KCAP=1      : causal K-range cap, nchunk = (row0+128)/32
// All call sites guarantee nchunk >= 4.
// ---------------------------------------------------------------------------
#define TILE_B    10240           // 128 rows x 80 B
#define STAGE_B   (4 * TILE_B)    // Ahi, Alo, Bhi, Blo
#define NSTAGE    2
#define GEMM_SMEM (NSTAGE * STAGE_B)   // 81920 B -> 2 CTAs/SM

template <int OUT_SPLIT, int TRI, int KCAP>
__global__ void __launch_bounds__(256, 2) gemm_mma_bf16x3(
    const __nv_bfloat16* __restrict__ Ahi, const __nv_bfloat16* __restrict__ Alo,
    const __nv_bfloat16* __restrict__ Bhi, const __nv_bfloat16* __restrict__ Blo,
    float* __restrict__ C, __nv_bfloat16* __restrict__ Chi, __nv_bfloat16* __restrict__ Clo,
    int M, int N, int K, size_t sAz, size_t sBz, size_t sCz, float alpha)
{
    if (TRI && (int)blockIdx.x > (int)blockIdx.y) return;  // fully-masked tile

    extern __shared__ __align__(16) char smem[];
    const uint32_t sb = smem_u32(smem);
    const int tid  = threadIdx.x;
    const int lane = tid & 31;
    const int wid  = tid >> 5;
    const int wm   = wid & 3;    // 4 warps along M
    const int wn   = wid >> 2;   // 2 warps along N

    Ahi += (size_t)blockIdx.z * sAz;  Alo += (size_t)blockIdx.z * sAz;
    Bhi += (size_t)blockIdx.z * sBz;  Blo += (size_t)blockIdx.z * sBz;

    const int row0 = blockIdx.y * 128;
    const int col0 = blockIdx.x * 128;
    const int kEff = KCAP ? (row0 + 128 < K ? row0 + 128 : K) : K;
    const int nchunk = kEff >> 5;

    // per-chunk loader: 4 tiles of 128 rows x 32 bf16 (64 B), padded to 80 B
    auto load_chunk = [&](int c, int s) {
        const int k0 = c << 5;
        const __nv_bfloat16* srcs[4] = {
            Ahi + (size_t)row0 * K + k0, Alo + (size_t)row0 * K + k0,
            Bhi + (size_t)col0 * K + k0, Blo + (size_t)col0 * K + k0 };
        const uint32_t dbase = sb + s * STAGE_B;
        #pragma unroll
        for (int t = 0; t < 4; ++t) {
            #pragma unroll
            for (int rep = 0; rep < 2; ++rep) {
                int idx = tid + rep * 256;      // 0..511
                int r = idx >> 2;               // row 0..127
                int q = idx & 3;                // 16B quarter of the 64B row
                cp16(dbase + t * TILE_B + r * 80 + q * 16,
                     srcs[t] + (size_t)r * K + q * 8);
            }
        }
    };

    float acc[2][8][4];
    #pragma unroll
    for (int mi = 0; mi < 2; ++mi)
        #pragma unroll
        for (int ni = 0; ni < 8; ++ni)
            #pragma unroll
            for (int j = 0; j < 4; ++j) acc[mi][ni][j] = 0.f;

    // prologue: prefetch 1 chunk
    load_chunk(0, 0);
    asm volatile("cp.async.commit_group;" ::: "memory");

    const int r   = lane >> 2;          // fragment row
    const int kq2 = (lane & 3) * 2;     // fragment k pair

    for (int c = 0; c < nchunk; ++c) {
        if (c + 1 < nchunk) load_chunk(c + 1, (c + 1) & 1);
        asm volatile("cp.async.commit_group;" ::: "memory");
        asm volatile("cp.async.wait_group 1;" ::: "memory");
        __syncthreads();

        const uint32_t s0 = sb + (c & 1) * STAGE_B;

        #pragma unroll
        for (int ks = 0; ks < 2; ++ks) {
            const uint32_t kb = (uint32_t)(ks * 16 + kq2) * 2;   // byte offset in k
            uint32_t ah[2][4], al[2][4], bh[8][2], bl[8][2];

            #pragma unroll
            for (int mi = 0; mi < 2; ++mi) {
                uint32_t base = s0 + (uint32_t)(wm * 32 + mi * 16 + r) * 80 + kb;
                ah[mi][0] = lds32(base);        ah[mi][1] = lds32(base + 640);
                ah[mi][2] = lds32(base + 16);   ah[mi][3] = lds32(base + 656);
                base += TILE_B;
                al[mi][0] = lds32(base);        al[mi][1] = lds32(base + 640);
                al[mi][2] = lds32(base + 16);   al[mi][3] = lds32(base + 656);
            }
            #pragma unroll
            for (int ni = 0; ni < 8; ++ni) {
                uint32_t base = s0 + 2 * TILE_B + (uint32_t)(wn * 64 + ni * 8 + r) * 80 + kb;
                bh[ni][0] = lds32(base);        bh[ni][1] = lds32(base + 16);
                base += TILE_B;
                bl[ni][0] = lds32(base);        bl[ni][1] = lds32(base + 16);
            }

            // 3 precision terms across 16 independent accumulators
            #pragma unroll
            for (int mi = 0; mi < 2; ++mi)
                #pragma unroll
                for (int ni = 0; ni < 8; ++ni)
                    mma_bf16(acc[mi][ni], ah[mi], bh[ni]);
            #pragma unroll
            for (int mi = 0; mi < 2; ++mi)
                #pragma unroll
                for (int ni = 0; ni < 8; ++ni)
                    mma_bf16(acc[mi][ni], ah[mi], bl[ni]);
            #pragma unroll
            for (int mi = 0; mi < 2; ++mi)
                #pragma unroll
                for (int ni = 0; ni < 8; ++ni)
                    mma_bf16(acc[mi][ni], al[mi], bh[ni]);
        }
        __syncthreads();
    }

    // Epilogue
    #pragma unroll
    for (int mi = 0; mi < 2; ++mi) {
        const int rowA = row0 + wm * 32 + mi * 16 + r;
        #pragma unroll
        for (int ni = 0; ni < 8; ++ni) {
            const int col = col0 + wn * 64 + ni * 8 + kq2;
            float v0 = acc[mi][ni][0] * alpha;
            float v1 = acc[mi][ni][1] * alpha;
            float v2 = acc[mi][ni][2] * alpha;
            float v3 = acc[mi][ni][3] * alpha;
            if (OUT_SPLIT) {
                __nv_bfloat16* ph = Chi + (size_t)blockIdx.z * sCz;
                __nv_bfloat16* pl = Clo + (size_t)blockIdx.z * sCz;
                __nv_bfloat16 h0 = __float2bfloat16(v0), h1 = __float2bfloat16(v1);
                __nv_bfloat16 h2 = __float2bfloat16(v2), h3 = __float2bfloat16(v3);
                __nv_bfloat162 hp0; hp0.x = h0; hp0.y = h1;
                __nv_bfloat162 hp1; hp1.x = h2; hp1.y = h3;
                __nv_bfloat162 lp0, lp1;
                lp0.x = __float2bfloat16(v0 - __bfloat162float(h0));
                lp0.y = __float2bfloat16(v1 - __bfloat162float(h1));
                lp1.x = __float2bfloat16(v2 - __bfloat162float(h2));
                lp1.y = __float2bfloat16(v3 - __bfloat162float(h3));
                *(__nv_bfloat162*)(ph + (size_t)rowA * N + col)       = hp0;
                *(__nv_bfloat162*)(pl + (size_t)rowA * N + col)       = lp0;
                *(__nv_bfloat162*)(ph + (size_t)(rowA + 8) * N + col) = hp1;
                *(__nv_bfloat162*)(pl + (size_t)(rowA + 8) * N + col) = lp1;
            } else {
                float* pc = C + (size_t)blockIdx.z * sCz;
                float2 f0 = {v0, v1}, f1 = {v2, v3};
                *(float2*)(pc + (size_t)rowA * N + col)       = f0;
                *(float2*)(pc + (size_t)(rowA + 8) * N + col) = f1;
            }
        }
    }
}

// ---------------------------------------------------------------------------
// fp32 -> bf16 hi/lo split (elementwise, vectorized)
// ---------------------------------------------------------------------------
__global__ void split_f32(const float* __restrict__ src,
                          __nv_bfloat16* __restrict__ hi,
                          __nv_bfloat16* __restrict__ lo, int n4)
{
    int i = blockIdx.x * blockDim.x + threadIdx.x;
    if (i >= n4) return;
    float4 v = ((const float4*)src)[i];
    __nv_bfloat16 h0 = __float2bfloat16(v.x), h1 = __float2bfloat16(v.y);
    __nv_bfloat16 h2 = __float2bfloat16(v.z), h3 = __float2bfloat16(v.w);
    __nv_bfloat162 hp0; hp0.x = h0; hp0.y = h1;
    __nv_bfloat162 hp1; hp1.x = h2; hp1.y = h3;
    __nv_bfloat162 lp0, lp1;
    lp0.x = __float2bfloat16(v.x - __bfloat162float(h0));
    lp0.y = __float2bfloat16(v.y - __bfloat162float(h1));
    lp1.x = __float2bfloat16(v.z - __bfloat162float(h2));
    lp1.y = __float2bfloat16(v.w - __bfloat162float(h3));
    ((__nv_bfloat162*)hi)[2 * i]     = hp0;
    ((__nv_bfloat162*)hi)[2 * i + 1] = hp1;
    ((__nv_bfloat162*)lo)[2 * i]     = lp0;
    ((__nv_bfloat162*)lo)[2 * i + 1] = lp1;
}

// ---------------------------------------------------------------------------
// fp32 [R,C] -> transposed bf16 hi/lo [C,R] (32x32 smem tile)
// ---------------------------------------------------------------------------
__global__ void transpose_split(const float* __restrict__ src,
                                __nv_bfloat16* __restrict__ hi,
                                __nv_bfloat16* __restrict__ lo,
                                int R, int C, size_t sSrc, size_t sDst)
{
    __shared__ float t[32][33];
    src += (size_t)blockIdx.z * sSrc;
    const int tx = threadIdx.x, ty = threadIdx.y;
    const int x  = blockIdx.x * 32 + tx;
    const int y0 = blockIdx.y * 32 + ty;
    #pragma unroll
    for (int i = 0; i < 32; i += 8)
        t[ty + i][tx] = src[(size_t)(y0 + i) * C + x];
    __syncthreads();
    const int ox  = blockIdx.y * 32 + tx;
    const int oy0 = blockIdx.x * 32 + ty;
    #pragma unroll
    for (int i = 0; i < 32; i += 8) {
        float v = t[tx][ty + i];
        __nv_bfloat16 h = __float2bfloat16(v);
        size_t idx = (size_t)blockIdx.z * sDst + (size_t)(oy0 + i) * R + ox;
        hi[idx] = h;
        lo[idx] = __float2bfloat16(v - __bfloat162float(h));
    }
}

// ---------------------------------------------------------------------------
// Causal softmax: reads fp32 scores (j<=i only), writes bf16 hi/lo P.
// Only writes j < blockend(i) — PV's causal K-cap never reads beyond the
// diagonal 128-block, so the rest of the row can stay garbage.
// ---------------------------------------------------------------------------
__global__ __launch_bounds__(256) void softmax_causal_split(
    const float* __restrict__ S,
    __nv_bfloat16* __restrict__ Phi, __nv_bfloat16* __restrict__ Plo)
{
    const int i = blockIdx.x;
    const int b = blockIdx.y;
    const size_t base = ((size_t)b * SLEN + i) * SLEN;
    const float* row = S + base;
    const int limit = ((i >> 7) + 1) << 7;   // end of diagonal 128-block

    __shared__ float sh[SLEN];
    __shared__ float red[256];
    const int tid = threadIdx.x;

    float mx = -1e30f;
    for (int j = tid; j < limit; j += 256) {
        float v = (j <= i) ? row[j] : -1e30f;
        sh[j] = v;
        mx = fmaxf(mx, v);
    }
    red[tid] = mx;
    __syncthreads();
    for (int s = 128; s > 0; s >>= 1) {
        if (tid < s) red[tid] = fmaxf(red[tid], red[tid + s]);
        __syncthreads();
    }
    mx = red[0];
    __syncthreads();

    float sum = 0.f;
    for (int j = tid; j < limit; j += 256) {
        float e = (j <= i) ? expf(sh[j] - mx) : 0.f;
        sh[j] = e;
        sum += e;
    }
    red[tid] = sum;
    __syncthreads();
    for (int s = 128; s > 0; s >>= 1) {
        if (tid < s) red[tid] += red[tid + s];
        __syncthreads();
    }
    const float inv = 1.f / red[0];
    __syncthreads();

    for (int j = tid; j < limit; j += 256) {
        float p = sh[j] * inv;
        __nv_bfloat16 h = __float2bfloat16(p);
        Phi[base + j] = h;
        Plo[base + j] = __float2bfloat16(p - __bfloat162float(h));
    }
}

// ---------------------------------------------------------------------------
extern "C" void kernel_launch(void* const* d_in, const int* in_sizes, int n_in,
                              void* d_out, int out_size)
{
    const float* X  = (const float*)d_in[0];
    const float* Wq = (const float*)d_in[1];
    const float* Wk = (const float*)d_in[2];
    const float* Wv = (const float*)d_in[3];
    float* out = (float*)d_out;

    __nv_bfloat16 *Xhi, *Xlo, *Wthi, *Wtlo, *Qhi, *Qlo, *Khi, *Klo;
    __nv_bfloat16 *Vthi, *Vtlo, *Phi, *Plo;
    float *Vf, *Sc;
    cudaGetSymbolAddress((void**)&Xhi, g_Xhi);
    cudaGetSymbolAddress((void**)&Xlo, g_Xlo);
    cudaGetSymbolAddress((void**)&Wthi, g_Wthi);
    cudaGetSymbolAddress((void**)&Wtlo, g_Wtlo);
    cudaGetSymbolAddress((void**)&Qhi, g_Qhi);
    cudaGetSymbolAddress((void**)&Qlo, g_Qlo);
    cudaGetSymbolAddress((void**)&Khi, g_Khi);
    cudaGetSymbolAddress((void**)&Klo, g_Klo);
    cudaGetSymbolAddress((void**)&Vf,  g_Vf);
    cudaGetSymbolAddress((void**)&Vthi, g_Vthi);
    cudaGetSymbolAddress((void**)&Vtlo, g_Vtlo);
    cudaGetSymbolAddress((void**)&Sc,  g_S);
    cudaGetSymbolAddress((void**)&Phi, g_Phi);
    cudaGetSymbolAddress((void**)&Plo, g_Plo);

    cudaFuncSetAttribute(gemm_mma_bf16x3<0,0,0>, cudaFuncAttributeMaxDynamicSharedMemorySize, GEMM_SMEM);
    cudaFuncSetAttribute(gemm_mma_bf16x3<1,0,0>, cudaFuncAttributeMaxDynamicSharedMemorySize, GEMM_SMEM);
    cudaFuncSetAttribute(gemm_mma_bf16x3<0,1,0>, cudaFuncAttributeMaxDynamicSharedMemorySize, GEMM_SMEM);
    cudaFuncSetAttribute(gemm_mma_bf16x3<0,0,1>, cudaFuncAttributeMaxDynamicSharedMemorySize, GEMM_SMEM);

    const size_t WSZ = (size_t)DM * DM;

    // 1. X -> bf16 split
    split_f32<<<(M_ALL * DM / 4 + 255) / 256, 256>>>(X, Xhi, Xlo, M_ALL * DM / 4);

    // 2. W -> transposed bf16 split ([n][k])
    dim3 tb(32, 8);
    transpose_split<<<dim3(DM / 32, DM / 32, 1), tb>>>(Wq, Wthi + 0 * WSZ, Wtlo + 0 * WSZ, DM, DM, 0, 0);
    transpose_split<<<dim3(DM / 32, DM / 32, 1), tb>>>(Wk, Wthi + 1 * WSZ, Wtlo + 1 * WSZ, DM, DM, 0, 0);
    transpose_split<<<dim3(DM / 32, DM / 32, 1), tb>>>(Wv, Wthi + 2 * WSZ, Wtlo + 2 * WSZ, DM, DM, 0, 0);

    // 3. QKV projections; Q,K epilogue emits bf16 split directly
    dim3 gq(DM / 128, M_ALL / 128, 1);
    gemm_mma_bf16x3<1,0,0><<<gq, 256, GEMM_SMEM>>>(Xhi, Xlo, Wthi + 0 * WSZ, Wtlo + 0 * WSZ,
                                                   nullptr, Qhi, Qlo, M_ALL, DM, DM, 0, 0, 0, 1.f);
    gemm_mma_bf16x3<1,0,0><<<gq, 256, GEMM_SMEM>>>(Xhi, Xlo, Wthi + 1 * WSZ, Wtlo + 1 * WSZ,
                                                   nullptr, Khi, Klo, M_ALL, DM, DM, 0, 0, 0, 1.f);
    gemm_mma_bf16x3<0,0,0><<<gq, 256, GEMM_SMEM>>>(Xhi, Xlo, Wthi + 2 * WSZ, Wtlo + 2 * WSZ,
                                                   Vf, nullptr, nullptr, M_ALL, DM, DM, 0, 0, 0, 1.f);

    // 4. V -> per-batch transposed bf16 split ([e][s])
    transpose_split<<<dim3(DM / 32, SLEN / 32, BATCH), tb>>>(
        Vf, Vthi, Vtlo, SLEN, DM, (size_t)SLEN * DM, (size_t)DM * SLEN);

    // 5. Scores: S = (Q @ K^T) / 32, lower-triangle tiles only (TRI=1)
    dim3 gs(SLEN / 128, SLEN / 128, BATCH);
    gemm_mma_bf16x3<0,1,0><<<gs, 256, GEMM_SMEM>>>(Qhi, Qlo, Khi, Klo, Sc, nullptr, nullptr,
                                                   SLEN, SLEN, DM,
                                                   (size_t)SLEN * DM, (size_t)SLEN * DM,
                                                   (size_t)SLEN * SLEN, 1.f / 32.f);

    // 6. Causal softmax -> bf16-split P (writes only up to diagonal block end)
    softmax_causal_split<<<dim3(SLEN, BATCH), 256>>>(Sc, Phi, Plo);

    // 7. Output: out = P @ V^T with causal K-cap (KCAP=1)
    dim3 go(DM / 128, SLEN / 128, BATCH);
    gemm_mma_bf16x3<0,0,1><<<go, 256, GEMM_SMEM>>>(Phi, Plo, Vthi, Vtlo, out, nullptr, nullptr,
                                                   SLEN, DM, SLEN,
                                                   (size_t)SLEN * SLEN, (size_t)DM * SLEN,
                                                   (size_t)SLEN * DM, 1.f);
}

// round 17
// speedup vs baseline: 1.2885x; 1.2863x over previous
#include <cuda_runtime.h>
#include <cuda_fp16.h>
#include <cstdint>

#define BATCH 4
#define SLEN  2048
#define DM    1024
#define M_ALL (BATCH * SLEN)   // 8192

// ---------------------------------------------------------------------------
// Scratch (device globals — no runtime allocation allowed)
// ---------------------------------------------------------------------------
__device__ __half g_Xhi[M_ALL * DM];
__device__ __half g_Xlo[M_ALL * DM];
__device__ __half g_Wt [3][DM * DM];          // W^T, single fp16
__device__ __half g_Qhi[M_ALL * DM];
__device__ __half g_Qlo[M_ALL * DM];
__device__ __half g_Khi[M_ALL * DM];
__device__ __half g_Klo[M_ALL * DM];
__device__ float  g_Vf [M_ALL * DM];
__device__ __half g_Vt [(size_t)BATCH * DM * SLEN];   // V^T, single fp16
__device__ float  g_S  [(size_t)BATCH * SLEN * SLEN];
__device__ __half g_Phi[(size_t)BATCH * SLEN * SLEN];
__device__ __half g_Plo[(size_t)BATCH * SLEN * SLEN];

// ---------------------------------------------------------------------------
// Helpers (base-PTX only: mma.sync + cp.async)
// ---------------------------------------------------------------------------
__device__ __forceinline__ uint32_t smem_u32(const void* p) {
    uint32_t a;
    asm("{ .reg .u64 t; cvta.to.shared.u64 t, %1; cvt.u32.u64 %0, t; }"
        : "=r"(a) : "l"(p));
    return a;
}

__device__ __forceinline__ uint32_t lds32(uint32_t addr) {
    uint32_t v;
    asm volatile("ld.shared.b32 %0, [%1];" : "=r"(v) : "r"(addr));
    return v;
}

__device__ __forceinline__ void cp16(uint32_t dst, const void* src) {
    asm volatile("cp.async.cg.shared.global [%0], [%1], 16;"
                 :: "r"(dst), "l"(src) : "memory");
}

__device__ __forceinline__ void mma_f16(float* c, const uint32_t* a, const uint32_t* b) {
    asm volatile(
        "mma.sync.aligned.m16n8k16.row.col.f32.f16.f16.f32 "
        "{%0,%1,%2,%3}, {%4,%5,%6,%7}, {%8,%9}, {%0,%1,%2,%3};"
        : "+f"(c[0]), "+f"(c[1]), "+f"(c[2]), "+f"(c[3])
        : "r"(a[0]), "r"(a[1]), "r"(a[2]), "r"(a[3]), "r"(b[0]), "r"(b[1]));
}

// ---------------------------------------------------------------------------
// HMMA fp16 split GEMM:  C[M,N] = alpha * (A_hi+A_lo)[M,K] @ op(B)[N,K]^T
//   TERMS=2 : B is single fp16            -> ah*b + al*b         (2 MMAs)
//   TERMS=3 : B is hi/lo fp16 pair        -> ah*bh + ah*bl + al*bh (3 MMAs)
// Both operands K-major. CTA tile 128x128, K-chunk 32, 8 warps (warp tile
// 32x64), 2-stage cp.async pipeline, 2 CTAs/SM. 80B-padded SMEM rows.
//   OUT_SPLIT=1 : epilogue emits fp16 hi/lo pair instead of fp32
//   TRI=1       : skip CTAs above the diagonal (scores QK^T, masked anyway)
//   KCAP=1      : causal K-range cap, nchunk = (row0+128)/32
// ---------------------------------------------------------------------------
#define TILE_B 10240              // 128 rows x 80 B

template <int OUT_SPLIT, int TERMS, int TRI, int KCAP>
__global__ void __launch_bounds__(256, 2) gemm_mma_f16(
    const __half* __restrict__ Ahi, const __half* __restrict__ Alo,
    const __half* __restrict__ Bhi, const __half* __restrict__ Blo,
    float* __restrict__ C, __half* __restrict__ Chi, __half* __restrict__ Clo,
    int M, int N, int K, size_t sAz, size_t sBz, size_t sCz, float alpha)
{
    if (TRI && (int)blockIdx.x > (int)blockIdx.y) return;  // fully-masked tile

    constexpr int TILES   = TERMS + 1;          // Ahi, Alo, B (, Blo)
    constexpr int STAGE_B = TILES * TILE_B;

    extern __shared__ __align__(16) char smem[];
    const uint32_t sb = smem_u32(smem);
    const int tid  = threadIdx.x;
    const int lane = tid & 31;
    const int wid  = tid >> 5;
    const int wm   = wid & 3;    // 4 warps along M
    const int wn   = wid >> 2;   // 2 warps along N

    Ahi += (size_t)blockIdx.z * sAz;  Alo += (size_t)blockIdx.z * sAz;
    Bhi += (size_t)blockIdx.z * sBz;
    if (TERMS == 3) Blo += (size_t)blockIdx.z * sBz;

    const int row0 = blockIdx.y * 128;
    const int col0 = blockIdx.x * 128;
    const int kEff = KCAP ? (row0 + 128 < K ? row0 + 128 : K) : K;
    const int nchunk = kEff >> 5;

    // per-chunk loader: TILES tiles of 128 rows x 32 fp16 (64 B), padded to 80 B
    auto load_chunk = [&](int c, int s) {
        const int k0 = c << 5;
        const __half* srcs[4];
        srcs[0] = Ahi + (size_t)row0 * K + k0;
        srcs[1] = Alo + (size_t)row0 * K + k0;
        srcs[2] = Bhi + (size_t)col0 * K + k0;
        if (TERMS == 3) srcs[3] = Blo + (size_t)col0 * K + k0;
        const uint32_t dbase = sb + s * STAGE_B;
        #pragma unroll
        for (int t = 0; t < TILES; ++t) {
            #pragma unroll
            for (int rep = 0; rep < 2; ++rep) {
                int idx = tid + rep * 256;      // 0..511
                int r = idx >> 2;               // row 0..127
                int q = idx & 3;                // 16B quarter of the 64B row
                cp16(dbase + t * TILE_B + r * 80 + q * 16,
                     srcs[t] + (size_t)r * K + q * 8);
            }
        }
    };

    float acc[2][8][4];
    #pragma unroll
    for (int mi = 0; mi < 2; ++mi)
        #pragma unroll
        for (int ni = 0; ni < 8; ++ni)
            #pragma unroll
            for (int j = 0; j < 4; ++j) acc[mi][ni][j] = 0.f;

    // prologue: prefetch 1 chunk
    load_chunk(0, 0);
    asm volatile("cp.async.commit_group;" ::: "memory");

    const int r   = lane >> 2;          // fragment row
    const int kq2 = (lane & 3) * 2;     // fragment k pair

    for (int c = 0; c < nchunk; ++c) {
        if (c + 1 < nchunk) load_chunk(c + 1, (c + 1) & 1);
        asm volatile("cp.async.commit_group;" ::: "memory");
        asm volatile("cp.async.wait_group 1;" ::: "memory");
        __syncthreads();

        const uint32_t s0 = sb + (c & 1) * STAGE_B;

        #pragma unroll
        for (int ks = 0; ks < 2; ++ks) {
            const uint32_t kb = (uint32_t)(ks * 16 + kq2) * 2;   // byte offset in k
            uint32_t ah[2][4], al[2][4], bh[8][2], bl[8][2];

            #pragma unroll
            for (int mi = 0; mi < 2; ++mi) {
                uint32_t base = s0 + (uint32_t)(wm * 32 + mi * 16 + r) * 80 + kb;
                ah[mi][0] = lds32(base);        ah[mi][1] = lds32(base + 640);
                ah[mi][2] = lds32(base + 16);   ah[mi][3] = lds32(base + 656);
                base += TILE_B;
                al[mi][0] = lds32(base);        al[mi][1] = lds32(base + 640);
                al[mi][2] = lds32(base + 16);   al[mi][3] = lds32(base + 656);
            }
            #pragma unroll
            for (int ni = 0; ni < 8; ++ni) {
                uint32_t base = s0 + 2 * TILE_B + (uint32_t)(wn * 64 + ni * 8 + r) * 80 + kb;
                bh[ni][0] = lds32(base);        bh[ni][1] = lds32(base + 16);
                if (TERMS == 3) {
                    base += TILE_B;
                    bl[ni][0] = lds32(base);    bl[ni][1] = lds32(base + 16);
                }
            }

            #pragma unroll
            for (int mi = 0; mi < 2; ++mi)
                #pragma unroll
                for (int ni = 0; ni < 8; ++ni)
                    mma_f16(acc[mi][ni], ah[mi], bh[ni]);
            #pragma unroll
            for (int mi = 0; mi < 2; ++mi)
                #pragma unroll
                for (int ni = 0; ni < 8; ++ni)
                    mma_f16(acc[mi][ni], al[mi], bh[ni]);
            if (TERMS == 3) {
                #pragma unroll
                for (int mi = 0; mi < 2; ++mi)
                    #pragma unroll
                    for (int ni = 0; ni < 8; ++ni)
                        mma_f16(acc[mi][ni], ah[mi], bl[ni]);
            }
        }
        __syncthreads();
    }

    // Epilogue
    #pragma unroll
    for (int mi = 0; mi < 2; ++mi) {
        const int rowA = row0 + wm * 32 + mi * 16 + r;
        #pragma unroll
        for (int ni = 0; ni < 8; ++ni) {
            const int col = col0 + wn * 64 + ni * 8 + kq2;
            float v0 = acc[mi][ni][0] * alpha;
            float v1 = acc[mi][ni][1] * alpha;
            float v2 = acc[mi][ni][2] * alpha;
            float v3 = acc[mi][ni][3] * alpha;
            if (OUT_SPLIT) {
                __half* ph = Chi + (size_t)blockIdx.z * sCz;
                __half* pl = Clo + (size_t)blockIdx.z * sCz;
                __half h0 = __float2half_rn(v0), h1 = __float2half_rn(v1);
                __half h2 = __float2half_rn(v2), h3 = __float2half_rn(v3);
                __half2 hp0 = __halves2half2(h0, h1);
                __half2 hp1 = __halves2half2(h2, h3);
                __half2 lp0 = __halves2half2(__float2half_rn(v0 - __half2float(h0)),
                                             __float2half_rn(v1 - __half2float(h1)));
                __half2 lp1 = __halves2half2(__float2half_rn(v2 - __half2float(h2)),
                                             __float2half_rn(v3 - __half2float(h3)));
                *(__half2*)(ph + (size_t)rowA * N + col)       = hp0;
                *(__half2*)(pl + (size_t)rowA * N + col)       = lp0;
                *(__half2*)(ph + (size_t)(rowA + 8) * N + col) = hp1;
                *(__half2*)(pl + (size_t)(rowA + 8) * N + col) = lp1;
            } else {
                float* pc = C + (size_t)blockIdx.z * sCz;
                float2 f0 = {v0, v1}, f1 = {v2, v3};
                *(float2*)(pc + (size_t)rowA * N + col)       = f0;
                *(float2*)(pc + (size_t)(rowA + 8) * N + col) = f1;
            }
        }
    }
}

// ---------------------------------------------------------------------------
// fp32 -> fp16 hi/lo split (elementwise, vectorized)
// ---------------------------------------------------------------------------
__global__ void split_f32_h(const float* __restrict__ src,
                            __half* __restrict__ hi,
                            __half* __restrict__ lo, int n4)
{
    int i = blockIdx.x * blockDim.x + threadIdx.x;
    if (i >= n4) return;
    float4 v = ((const float4*)src)[i];
    __half h0 = __float2half_rn(v.x), h1 = __float2half_rn(v.y);
    __half h2 = __float2half_rn(v.z), h3 = __float2half_rn(v.w);
    __half2 hp0 = __halves2half2(h0, h1);
    __half2 hp1 = __halves2half2(h2, h3);
    __half2 lp0 = __halves2half2(__float2half_rn(v.x - __half2float(h0)),
                                 __float2half_rn(v.y - __half2float(h1)));
    __half2 lp1 = __halves2half2(__float2half_rn(v.z - __half2float(h2)),
                                 __float2half_rn(v.w - __half2float(h3)));
    ((__half2*)hi)[2 * i]     = hp0;
    ((__half2*)hi)[2 * i + 1] = hp1;
    ((__half2*)lo)[2 * i]     = lp0;
    ((__half2*)lo)[2 * i + 1] = lp1;
}

// ---------------------------------------------------------------------------
// fp32 [R,C] -> transposed single fp16 [C,R] (32x32 smem tile)
// ---------------------------------------------------------------------------
__global__ void transpose_h(const float* __restrict__ src,
                            __half* __restrict__ dst,
                            int R, int C, size_t sSrc, size_t sDst)
{
    __shared__ float t[32][33];
    src += (size_t)blockIdx.z * sSrc;
    const int tx = threadIdx.x, ty = threadIdx.y;
    const int x  = blockIdx.x * 32 + tx;
    const int y0 = blockIdx.y * 32 + ty;
    #pragma unroll
    for (int i = 0; i < 32; i += 8)
        t[ty + i][tx] = src[(size_t)(y0 + i) * C + x];
    __syncthreads();
    const int ox  = blockIdx.y * 32 + tx;
    const int oy0 = blockIdx.x * 32 + ty;
    #pragma unroll
    for (int i = 0; i < 32; i += 8) {
        size_t idx = (size_t)blockIdx.z * sDst + (size_t)(oy0 + i) * R + ox;
        dst[idx] = __float2half_rn(t[tx][ty + i]);
    }
}

// ---------------------------------------------------------------------------
// Causal softmax: reads fp32 scores (j<=i only), writes fp16 hi/lo P.
// Only writes j < blockend(i) — PV's causal K-cap never reads beyond the
// diagonal 128-block, so the rest of the row can stay garbage.
// ---------------------------------------------------------------------------
__global__ __launch_bounds__(256) void softmax_causal_split(
    const float* __restrict__ S,
    __half* __restrict__ Phi, __half* __restrict__ Plo)
{
    const int i = blockIdx.x;
    const int b = blockIdx.y;
    const size_t base = ((size_t)b * SLEN + i) * SLEN;
    const float* row = S + base;
    const int limit = ((i >> 7) + 1) << 7;   // end of diagonal 128-block

    __shared__ float sh[SLEN];
    __shared__ float red[256];
    const int tid = threadIdx.x;

    float mx = -1e30f;
    for (int j = tid; j < limit; j += 256) {
        float v = (j <= i) ? row[j] : -1e30f;
        sh[j] = v;
        mx = fmaxf(mx, v);
    }
    red[tid] = mx;
    __syncthreads();
    for (int s = 128; s > 0; s >>= 1) {
        if (tid < s) red[tid] = fmaxf(red[tid], red[tid + s]);
        __syncthreads();
    }
    mx = red[0];
    __syncthreads();

    float sum = 0.f;
    for (int j = tid; j < limit; j += 256) {
        float e = (j <= i) ? expf(sh[j] - mx) : 0.f;
        sh[j] = e;
        sum += e;
    }
    red[tid] = sum;
    __syncthreads();
    for (int s = 128; s > 0; s >>= 1) {
        if (tid < s) red[tid] += red[tid + s];
        __syncthreads();
    }
    const float inv = 1.f / red[0];
    __syncthreads();

    for (int j = tid; j < limit; j += 256) {
        float p = sh[j] * inv;
        __half h = __float2half_rn(p);
        Phi[base + j] = h;
        Plo[base + j] = __float2half_rn(p - __half2float(h));
    }
}

// ---------------------------------------------------------------------------
extern "C" void kernel_launch(void* const* d_in, const int* in_sizes, int n_in,
                              void* d_out, int out_size)
{
    const float* X  = (const float*)d_in[0];
    const float* Wq = (const float*)d_in[1];
    const float* Wk = (const float*)d_in[2];
    const float* Wv = (const float*)d_in[3];
    float* out = (float*)d_out;

    __half *Xhi, *Xlo, *Wt, *Qhi, *Qlo, *Khi, *Klo, *Vt, *Phi, *Plo;
    float *Vf, *Sc;
    cudaGetSymbolAddress((void**)&Xhi, g_Xhi);
    cudaGetSymbolAddress((void**)&Xlo, g_Xlo);
    cudaGetSymbolAddress((void**)&Wt,  g_Wt);
    cudaGetSymbolAddress((void**)&Qhi, g_Qhi);
    cudaGetSymbolAddress((void**)&Qlo, g_Qlo);
    cudaGetSymbolAddress((void**)&Khi, g_Khi);
    cudaGetSymbolAddress((void**)&Klo, g_Klo);
    cudaGetSymbolAddress((void**)&Vf,  g_Vf);
    cudaGetSymbolAddress((void**)&Vt,  g_Vt);
    cudaGetSymbolAddress((void**)&Sc,  g_S);
    cudaGetSymbolAddress((void**)&Phi, g_Phi);
    cudaGetSymbolAddress((void**)&Plo, g_Plo);

    const int SM2 = 2 * 3 * TILE_B;   // 2-term: 3 tiles/stage, 2 stages = 61440
    const int SM3 = 2 * 4 * TILE_B;   // 3-term: 4 tiles/stage, 2 stages = 81920
    cudaFuncSetAttribute(gemm_mma_f16<1,2,0,0>, cudaFuncAttributeMaxDynamicSharedMemorySize, SM2);
    cudaFuncSetAttribute(gemm_mma_f16<0,2,0,0>, cudaFuncAttributeMaxDynamicSharedMemorySize, SM2);
    cudaFuncSetAttribute(gemm_mma_f16<0,3,1,0>, cudaFuncAttributeMaxDynamicSharedMemorySize, SM3);
    cudaFuncSetAttribute(gemm_mma_f16<0,2,0,1>, cudaFuncAttributeMaxDynamicSharedMemorySize, SM2);

    const size_t WSZ = (size_t)DM * DM;

    // 1. X -> fp16 hi/lo split
    split_f32_h<<<(M_ALL * DM / 4 + 255) / 256, 256>>>(X, Xhi, Xlo, M_ALL * DM / 4);

    // 2. W -> transposed single fp16 ([n][k])
    dim3 tb(32, 8);
    transpose_h<<<dim3(DM / 32, DM / 32, 1), tb>>>(Wq, Wt + 0 * WSZ, DM, DM, 0, 0);
    transpose_h<<<dim3(DM / 32, DM / 32, 1), tb>>>(Wk, Wt + 1 * WSZ, DM, DM, 0, 0);
    transpose_h<<<dim3(DM / 32, DM / 32, 1), tb>>>(Wv, Wt + 2 * WSZ, DM, DM, 0, 0);

    // 3. QKV projections, 2-term (B = single fp16 W); Q,K emit fp16 split
    dim3 gq(DM / 128, M_ALL / 128, 1);
    gemm_mma_f16<1,2,0,0><<<gq, 256, SM2>>>(Xhi, Xlo, Wt + 0 * WSZ, nullptr,
                                            nullptr, Qhi, Qlo, M_ALL, DM, DM, 0, 0, 0, 1.f);
    gemm_mma_f16<1,2,0,0><<<gq, 256, SM2>>>(Xhi, Xlo, Wt + 1 * WSZ, nullptr,
                                            nullptr, Khi, Klo, M_ALL, DM, DM, 0, 0, 0, 1.f);
    gemm_mma_f16<0,2,0,0><<<gq, 256, SM2>>>(Xhi, Xlo, Wt + 2 * WSZ, nullptr,
                                            Vf, nullptr, nullptr, M_ALL, DM, DM, 0, 0, 0, 1.f);

    // 4. V -> per-batch transposed single fp16 ([e][s])
    transpose_h<<<dim3(DM / 32, SLEN / 32, BATCH), tb>>>(
        Vf, Vt, SLEN, DM, (size_t)SLEN * DM, (size_t)DM * SLEN);

    // 5. Scores: S = (Q @ K^T) / 32, 3-term (exp-sensitive), lower-tri only
    dim3 gs(SLEN / 128, SLEN / 128, BATCH);
    gemm_mma_f16<0,3,1,0><<<gs, 256, SM3>>>(Qhi, Qlo, Khi, Klo, Sc, nullptr, nullptr,
                                            SLEN, SLEN, DM,
                                            (size_t)SLEN * DM, (size_t)SLEN * DM,
                                            (size_t)SLEN * SLEN, 1.f / 32.f);

    // 6. Causal softmax -> fp16-split P (writes only up to diagonal block end)
    softmax_causal_split<<<dim3(SLEN, BATCH), 256>>>(Sc, Phi, Plo);

    // 7. Output: out = P @ V^T, 2-term (B = single fp16 V), causal K-cap
    dim3 go(DM / 128, SLEN / 128, BATCH);
    gemm_mma_f16<0,2,0,1><<<go, 256, SM2>>>(Phi, Plo, Vt, nullptr, out, nullptr, nullptr,
                                            SLEN, DM, SLEN,
                                            (size_t)SLEN * SLEN, (size_t)DM * SLEN,
                                            (size_t)SLEN * DM, 1.f);
}